// round 17
// baseline (speedup 1.0000x reference)
#include <cuda_runtime.h>
#include <cuda_bf16.h>
#include <cstdint>
#include <cstddef>

#define B_ 4096
#define T_ 168
#define D_ 64
#define H_ 128
#define G_ 384   // 3*H

// ---------------------------------------------------------------------------
// helpers
// ---------------------------------------------------------------------------
__device__ __forceinline__ float tanh_hw(float x) {
    float r;
    asm("tanh.approx.f32 %0, %1;" : "=f"(r) : "f"(x));
    return r;
}
__device__ __forceinline__ float fast_sigmoid(float x) {
    return fmaf(0.5f, tanh_hw(0.5f * x), 0.5f);
}

// warp-level bf16 tensor-core mma (HMMA path, plain sm_100-legal PTX)
#define MMA_BF16(c, a, b) \
    asm volatile("mma.sync.aligned.m16n8k16.row.col.f32.bf16.bf16.f32 " \
        "{%0,%1,%2,%3}, {%4,%5,%6,%7}, {%8,%9}, {%0,%1,%2,%3};" \
        : "+f"((c)[0]), "+f"((c)[1]), "+f"((c)[2]), "+f"((c)[3]) \
        : "r"((a)[0]), "r"((a)[1]), "r"((a)[2]), "r"((a)[3]), \
          "r"((b).x), "r"((b).y))

// ldmatrix x4: loads the full m16k16 A fragment (4 8x8 tiles) in one op.
#define LDSM_X4(r, addr) \
    asm volatile("ldmatrix.sync.aligned.m8n8.x4.shared.b16 {%0,%1,%2,%3}, [%4];" \
        : "=r"((r)[0]), "=r"((r)[1]), "=r"((r)[2]), "=r"((r)[3]) : "r"(addr))

// ---------------------------------------------------------------------------
// FUSED kernel: GRU scan with gx computed in-step on tensor cores.
// 128 blocks x 256 threads (8 warps), 32 batch rows per block.
// A-fragments now loaded via ldmatrix.x4 (1 op per 16x16 tile, conflict-free
// thanks to pads 272/144 B = 4-bank row strides).
// ---------------------------------------------------------------------------
#define SWLO   0          // W_hh-lo fragments (98304 B)
#define SWIH   98304      // W_ih-hi fragments (49152)   [init: W_hh-hi staging]
#define SWIL   147456     // W_ih-lo fragments (49152)
#define SH_HI  196608     // h hi image, 32 x 272 B
#define SH_LO  205312     // h lo image
#define SX_HI  214016     // feats hi image, 32 x 144 B
#define SX_LO  218624     // feats lo image
#define SWY    223232     // wy fp32 [384]
#define SBRZ   224768     // b_ih+b_hh, gates 0..255 (r,z regions)
#define SBIN   225792     // b_ih, n region [128]
#define SBHN   226304     // b_hh, n region [128]
#define SWO    226816     // Wo [128]
#define SRED   227328     // 8 x 32 fp32
#define S_TOT  228352

__global__ void __launch_bounds__(256, 1)
fused_kernel(const float* __restrict__ feats, const float* __restrict__ h0,
             const float* __restrict__ y0, const float* __restrict__ W_ih,
             const float* __restrict__ W_hh, const float* __restrict__ b_ih,
             const float* __restrict__ b_hh, const float* __restrict__ Wo,
             const float* __restrict__ bo, float* __restrict__ out)
{
    extern __shared__ char smemS[];
    const int tid  = threadIdx.x;
    const int w    = tid >> 5;          // warp 0..7 (column group)
    const int lane = tid & 31;
    const int g    = lane >> 2;         // 0..7
    const int tg   = lane & 3;          // 0..3
    const int b0   = blockIdx.x * 32;

    float* sWyf  = (float*)(smemS + SWY);
    float* sBrzf = (float*)(smemS + SBRZ);
    float* sBinf = (float*)(smemS + SBIN);
    float* sBhnf = (float*)(smemS + SBHN);
    float* sWof  = (float*)(smemS + SWO);
    float* sRf   = (float*)(smemS + SRED);

    // ---- init: W_hh -> lo frags at SWLO (permanent), hi frags staged at SWIH ----
    for (int idx = tid; idx < G_ * H_; idx += 256) {
        int n = idx >> 7;
        int k = idx & 127;
        float wv = W_hh[idx];
        __nv_bfloat16 h16 = __float2bfloat16(wv);
        float lof = wv - __bfloat162float(h16);
        __nv_bfloat16 l16 = __float2bfloat16(lof);
        int region = n >> 7, off = n & 127;
        int ww = off >> 4, nt = (off >> 3) & 1, n8 = off & 7;
        int kstep = k >> 4, kk = k & 15;
        int reg  = kk >> 3;
        int tgi  = (kk & 7) >> 1;
        int half = kk & 1;
        int ln   = n8 * 4 + tgi;
        int fidx = ((ww * 3 + region) * 2 + nt) * 8 + kstep;
        int boff = fidx * 256 + ln * 8 + reg * 4 + half * 2;
        *(unsigned short*)(smemS + SWLO + boff) = __bfloat16_as_ushort(l16);
        *(unsigned short*)(smemS + SWIH + boff) = __bfloat16_as_ushort(h16);  // staging
    }
    // h0 images (pad 272: conflict-free frag loads)
    for (int i = tid; i < 32 * H_; i += 256) {
        int row = i >> 7, k = i & 127;
        float hv = h0[(size_t)b0 * H_ + i];
        __nv_bfloat16 h16 = __float2bfloat16(hv);
        float lof = hv - __bfloat162float(h16);
        *(unsigned short*)(smemS + SH_HI + row * 272 + k * 2) = __bfloat16_as_ushort(h16);
        *(unsigned short*)(smemS + SH_LO + row * 272 + k * 2) =
            __bfloat16_as_ushort(__float2bfloat16(lof));
    }
    for (int i = tid; i < G_; i += 256)
        sWyf[i] = W_ih[(size_t)i * (D_ + 1) + D_];
    for (int i = tid; i < 2 * H_; i += 256)
        sBrzf[i] = b_ih[i] + b_hh[i];
    for (int i = tid; i < H_; i += 256) {
        sBinf[i] = b_ih[2 * H_ + i];
        sBhnf[i] = b_hh[2 * H_ + i];
        sWof[i]  = Wo[i];
    }
    for (int i = tid; i < 8 * 32; i += 256)
        sRf[i] = (i < 32) ? y0[b0 + i] : 0.f;
    const float bo_v = bo[0];
    __syncthreads();

    const int colb0 = w * 16 + 2 * tg;

    // ---- W_hh-hi fragments -> persistent registers ----
    uint2 bhiR[3][2][8];
    #pragma unroll
    for (int region = 0; region < 3; region++)
        #pragma unroll
        for (int nt = 0; nt < 2; nt++)
            #pragma unroll
            for (int ks = 0; ks < 8; ks++) {
                int fb = (((w * 3 + region) * 2 + nt) * 8 + ks) * 256 + lane * 8;
                bhiR[region][nt][ks] = *(const uint2*)(smemS + SWIH + fb);
            }
    __syncthreads();

    // ---- overwrite staging with W_ih hi/lo fragments (4-kstep layout) ----
    for (int idx = tid; idx < G_ * D_; idx += 256) {
        int n = idx >> 6;
        int k = idx & 63;
        float wv = W_ih[(size_t)n * (D_ + 1) + k];
        __nv_bfloat16 h16 = __float2bfloat16(wv);
        float lof = wv - __bfloat162float(h16);
        __nv_bfloat16 l16 = __float2bfloat16(lof);
        int region = n >> 7, off = n & 127;
        int ww = off >> 4, nt = (off >> 3) & 1, n8 = off & 7;
        int kstep = k >> 4, kk = k & 15;
        int reg  = kk >> 3;
        int tgi  = (kk & 7) >> 1;
        int half = kk & 1;
        int ln   = n8 * 4 + tgi;
        int fidx = ((ww * 3 + region) * 2 + nt) * 4 + kstep;
        int boff = fidx * 256 + ln * 8 + reg * 4 + half * 2;
        *(unsigned short*)(smemS + SWIH + boff) = __bfloat16_as_ushort(h16);
        *(unsigned short*)(smemS + SWIL + boff) = __bfloat16_as_ushort(l16);
    }
    // feats image for t = 0
    {
        int r = tid >> 3, k0 = (tid & 7) * 8;
        const float* fp = feats + ((size_t)(b0 + r) * T_) * D_ + k0;
        float fs[8];
        #pragma unroll
        for (int j = 0; j < 8; j++) fs[j] = fp[j];
        #pragma unroll
        for (int j = 0; j < 4; j++) {
            __nv_bfloat162 hh = __floats2bfloat162_rn(fs[2 * j], fs[2 * j + 1]);
            float l0 = fs[2 * j]     - __bfloat162float(__low2bfloat16(hh));
            float l1 = fs[2 * j + 1] - __bfloat162float(__high2bfloat16(hh));
            __nv_bfloat162 ll = __floats2bfloat162_rn(l0, l1);
            int boff = r * 144 + k0 * 2 + j * 4;
            *(uint32_t*)(smemS + SX_HI + boff) = *(uint32_t*)&hh;
            *(uint32_t*)(smemS + SX_LO + boff) = *(uint32_t*)&ll;
        }
    }
    __syncthreads();

    // ---- per-thread ldmatrix base addresses ----
    const uint32_t sbase = (uint32_t)__cvta_generic_to_shared(smemS);
    const int lrow = (lane & 7) + ((lane >> 3) & 1) * 8;   // 0..15
    const int lcol = (lane >> 4) * 16;                      // 0 or 16
    uint32_t aH_hi[2], aH_lo[2], aX_hi[2], aX_lo[2];
    #pragma unroll
    for (int mt = 0; mt < 2; mt++) {
        aH_hi[mt] = sbase + SH_HI + (mt * 16 + lrow) * 272 + lcol;
        aH_lo[mt] = sbase + SH_LO + (mt * 16 + lrow) * 272 + lcol;
        aX_hi[mt] = sbase + SX_HI + (mt * 16 + lrow) * 144 + lcol;
        aX_lo[mt] = sbase + SX_LO + (mt * 16 + lrow) * 144 + lcol;
    }

    for (int t = 0; t < T_; t++) {
        // prefetch feats for t+1 into registers
        float4 fA, fB;
        if (t < T_ - 1) {
            const float* fp = feats + ((size_t)(b0 + (tid >> 3)) * T_ + (t + 1)) * D_
                            + (tid & 7) * 8;
            fA = *(const float4*)(fp);
            fB = *(const float4*)(fp + 4);
        }

        float c[2][3][2][4];      // h-part (regions r,z,n) + x-part (r,z)
        float cxn[2][2][4];       // x-part of n region (kept outside r*(.))
        #pragma unroll
        for (int mt = 0; mt < 2; mt++) {
            #pragma unroll
            for (int region = 0; region < 3; region++)
                #pragma unroll
                for (int nt = 0; nt < 2; nt++)
                    #pragma unroll
                    for (int q = 0; q < 4; q++) c[mt][region][nt][q] = 0.f;
            #pragma unroll
            for (int nt = 0; nt < 2; nt++)
                #pragma unroll
                for (int q = 0; q < 4; q++) cxn[mt][nt][q] = 0.f;
        }

        // ------ x-MMAs: x_t @ W_ih^T (4 ks, 3-product) ------
        #pragma unroll
        for (int ks = 0; ks < 4; ks++) {
            uint32_t axh[2][4], axl[2][4];
            #pragma unroll
            for (int mt = 0; mt < 2; mt++) {
                LDSM_X4(axh[mt], aX_hi[mt] + ks * 32);
                LDSM_X4(axl[mt], aX_lo[mt] + ks * 32);
            }
            #pragma unroll
            for (int region = 0; region < 3; region++)
                #pragma unroll
                for (int nt = 0; nt < 2; nt++) {
                    int fb = (((w * 3 + region) * 2 + nt) * 4 + ks) * 256 + lane * 8;
                    uint2 bih_ = *(const uint2*)(smemS + SWIH + fb);
                    uint2 bil_ = *(const uint2*)(smemS + SWIL + fb);
                    #pragma unroll
                    for (int mt = 0; mt < 2; mt++) {
                        float* dst = (region < 2) ? c[mt][region][nt] : cxn[mt][nt];
                        MMA_BF16(dst, axh[mt], bih_);
                        MMA_BF16(dst, axh[mt], bil_);
                        MMA_BF16(dst, axl[mt], bih_);
                    }
                }
        }

        // ------ h-MMAs: h @ W_hh^T (8 ks, 3-product, B-hi from regs) ------
        #pragma unroll
        for (int ks = 0; ks < 8; ks++) {
            uint32_t ahi[2][4], alo[2][4];
            #pragma unroll
            for (int mt = 0; mt < 2; mt++) {
                LDSM_X4(ahi[mt], aH_hi[mt] + ks * 32);
                LDSM_X4(alo[mt], aH_lo[mt] + ks * 32);
            }
            #pragma unroll
            for (int region = 0; region < 3; region++)
                #pragma unroll
                for (int nt = 0; nt < 2; nt++) {
                    int fb = (((w * 3 + region) * 2 + nt) * 8 + ks) * 256 + lane * 8;
                    uint2 blo = *(const uint2*)(smemS + SWLO + fb);
                    uint2 bhi = bhiR[region][nt][ks];
                    #pragma unroll
                    for (int mt = 0; mt < 2; mt++) {
                        MMA_BF16(c[mt][region][nt], ahi[mt], bhi);
                        MMA_BF16(c[mt][region][nt], ahi[mt], blo);
                        MMA_BF16(c[mt][region][nt], alo[mt], bhi);
                    }
                }
        }

        // ------ epilogue ------
        float2 wyc[3][2], brz[2][2], binc[2], bhnc[2], woc[2];
        #pragma unroll
        for (int region = 0; region < 3; region++)
            #pragma unroll
            for (int nt = 0; nt < 2; nt++)
                wyc[region][nt] = *(const float2*)(sWyf + region * 128 + colb0 + nt * 8);
        #pragma unroll
        for (int region = 0; region < 2; region++)
            #pragma unroll
            for (int nt = 0; nt < 2; nt++)
                brz[region][nt] = *(const float2*)(sBrzf + region * 128 + colb0 + nt * 8);
        #pragma unroll
        for (int nt = 0; nt < 2; nt++) {
            binc[nt] = *(const float2*)(sBinf + colb0 + nt * 8);
            bhnc[nt] = *(const float2*)(sBhnf + colb0 + nt * 8);
            woc[nt]  = *(const float2*)(sWof + colb0 + nt * 8);
        }

        float pacc[4] = {0.f, 0.f, 0.f, 0.f};
        uint32_t hhiN[2][2][2], hloN[2][2][2];
        #pragma unroll
        for (int mt = 0; mt < 2; mt++)
            #pragma unroll
            for (int rr = 0; rr < 2; rr++) {
                int row = mt * 16 + rr * 8 + g;
                float y = sRf[row] + sRf[32 + row] + sRf[64 + row] + sRf[96 + row]
                        + sRf[128 + row] + sRf[160 + row] + sRf[192 + row] + sRf[224 + row];
                if (t > 0 && w == 0 && tg == 0)
                    out[(size_t)(b0 + row) * T_ + (t - 1)] = y;
                #pragma unroll
                for (int nt = 0; nt < 2; nt++) {
                    int cb = (colb0 + nt * 8) * 2;
                    uint32_t hpw = *(const uint32_t*)(smemS + SH_HI + row * 272 + cb);
                    uint32_t lpw = *(const uint32_t*)(smemS + SH_LO + row * 272 + cb);
                    float hp0 = __bfloat162float(__ushort_as_bfloat16((unsigned short)(hpw)))
                              + __bfloat162float(__ushort_as_bfloat16((unsigned short)(lpw)));
                    float hp1 = __bfloat162float(__ushort_as_bfloat16((unsigned short)(hpw >> 16)))
                              + __bfloat162float(__ushort_as_bfloat16((unsigned short)(lpw >> 16)));

                    int i0 = rr * 2;
                    float r0 = fast_sigmoid(c[mt][0][nt][i0] + y * wyc[0][nt].x + brz[0][nt].x);
                    float z0 = fast_sigmoid(c[mt][1][nt][i0] + y * wyc[1][nt].x + brz[1][nt].x);
                    float n0 = tanh_hw(cxn[mt][nt][i0] + y * wyc[2][nt].x + binc[nt].x
                                       + r0 * (bhnc[nt].x + c[mt][2][nt][i0]));
                    float h0v = (1.f - z0) * n0 + z0 * hp0;

                    float r1 = fast_sigmoid(c[mt][0][nt][i0 + 1] + y * wyc[0][nt].y + brz[0][nt].y);
                    float z1 = fast_sigmoid(c[mt][1][nt][i0 + 1] + y * wyc[1][nt].y + brz[1][nt].y);
                    float n1 = tanh_hw(cxn[mt][nt][i0 + 1] + y * wyc[2][nt].y + binc[nt].y
                                       + r1 * (bhnc[nt].y + c[mt][2][nt][i0 + 1]));
                    float h1v = (1.f - z1) * n1 + z1 * hp1;

                    pacc[mt * 2 + rr] += h0v * woc[nt].x + h1v * woc[nt].y;

                    __nv_bfloat16 hb0 = __float2bfloat16(h0v);
                    __nv_bfloat16 hb1 = __float2bfloat16(h1v);
                    float l0 = h0v - __bfloat162float(hb0);
                    float l1 = h1v - __bfloat162float(hb1);
                    hhiN[mt][rr][nt] = (uint32_t)__bfloat16_as_ushort(hb0)
                                     | ((uint32_t)__bfloat16_as_ushort(hb1) << 16);
                    hloN[mt][rr][nt] = (uint32_t)__bfloat16_as_ushort(__float2bfloat16(l0))
                                     | ((uint32_t)__bfloat16_as_ushort(__float2bfloat16(l1)) << 16);
                }
            }
        __syncthreads();   // all reads of SH/SX/sRed done

        // store new h images
        #pragma unroll
        for (int mt = 0; mt < 2; mt++)
            #pragma unroll
            for (int rr = 0; rr < 2; rr++) {
                int row = mt * 16 + rr * 8 + g;
                #pragma unroll
                for (int nt = 0; nt < 2; nt++) {
                    int cb = (colb0 + nt * 8) * 2;
                    *(uint32_t*)(smemS + SH_HI + row * 272 + cb) = hhiN[mt][rr][nt];
                    *(uint32_t*)(smemS + SH_LO + row * 272 + cb) = hloN[mt][rr][nt];
                }
            }
        // store feats image for t+1
        if (t < T_ - 1) {
            int r = tid >> 3, k0 = (tid & 7) * 8;
            float fs[8] = {fA.x, fA.y, fA.z, fA.w, fB.x, fB.y, fB.z, fB.w};
            #pragma unroll
            for (int j = 0; j < 4; j++) {
                __nv_bfloat162 hh = __floats2bfloat162_rn(fs[2 * j], fs[2 * j + 1]);
                float l0 = fs[2 * j]     - __bfloat162float(__low2bfloat16(hh));
                float l1 = fs[2 * j + 1] - __bfloat162float(__high2bfloat16(hh));
                __nv_bfloat162 ll = __floats2bfloat162_rn(l0, l1);
                int boff = r * 144 + k0 * 2 + j * 4;
                *(uint32_t*)(smemS + SX_HI + boff) = *(uint32_t*)&hh;
                *(uint32_t*)(smemS + SX_LO + boff) = *(uint32_t*)&ll;
            }
        }
        // y partials
        #pragma unroll
        for (int i = 0; i < 4; i++) {
            pacc[i] += __shfl_xor_sync(0xffffffffu, pacc[i], 1);
            pacc[i] += __shfl_xor_sync(0xffffffffu, pacc[i], 2);
        }
        if (tg == 0) {
            float b_add = (w == 0) ? bo_v : 0.f;
            sRf[w * 32 + g]      = pacc[0] + b_add;
            sRf[w * 32 + g + 8]  = pacc[1] + b_add;
            sRf[w * 32 + g + 16] = pacc[2] + b_add;
            sRf[w * 32 + g + 24] = pacc[3] + b_add;
        }
        __syncthreads();
    }

    // flush final step's y
    if (w == 0 && tg == 0) {
        #pragma unroll
        for (int q = 0; q < 4; q++) {
            int row = q * 8 + g;
            float y = sRf[row] + sRf[32 + row] + sRf[64 + row] + sRf[96 + row]
                    + sRf[128 + row] + sRf[160 + row] + sRf[192 + row] + sRf[224 + row];
            out[(size_t)(b0 + row) * T_ + (T_ - 1)] = y;
        }
    }
}

// ---------------------------------------------------------------------------
extern "C" void kernel_launch(void* const* d_in, const int* in_sizes, int n_in,
                              void* d_out, int out_size)
{
    const float* feats = (const float*)d_in[0];
    const float* h0    = (const float*)d_in[1];
    const float* y0    = (const float*)d_in[2];
    const float* W_ih  = (const float*)d_in[3];
    const float* W_hh  = (const float*)d_in[4];
    const float* b_ih  = (const float*)d_in[5];
    const float* b_hh  = (const float*)d_in[6];
    const float* Wo    = (const float*)d_in[7];
    const float* bo    = (const float*)d_in[8];
    float* out = (float*)d_out;

    cudaFuncSetAttribute(fused_kernel, cudaFuncAttributeMaxDynamicSharedMemorySize, S_TOT);
    fused_kernel<<<B_ / 32, 256, S_TOT>>>(feats, h0, y0, W_ih, W_hh, b_ih, b_hh,
                                          Wo, bo, out);
}